// round 5
// baseline (speedup 1.0000x reference)
#include <cuda_runtime.h>

#define NROWS 1000000
#define HALF  (NROWS / 2)
#define TPB   128

typedef unsigned long long ull;

// ---- packed f32x2 helpers, register-pair ("l") constraints ------------------
__device__ __forceinline__ ull ffma2(ull a, ull b, ull c) {
    ull d;
    asm("fma.rn.f32x2 %0, %1, %2, %3;" : "=l"(d) : "l"(a), "l"(b), "l"(c));
    return d;
}
__device__ __forceinline__ ull pk(float x, float y) {
    ull r;
    asm("mov.b64 %0, {%1, %2};" : "=l"(r) : "f"(x), "f"(y));
    return r;
}
__device__ __forceinline__ float2 unpk(ull v) {
    float2 r;
    asm("mov.b64 {%0, %1}, %2;" : "=f"(r.x), "=f"(r.y) : "l"(v));
    return r;
}
// relu on both packed lanes via signed-int max(x,0): for IEEE-754 bits,
// x>=0 -> bits>=0 and order-preserving (max returns x); x<0 (or -0.0) ->
// bits<0 -> returns +0.0. Single asm block so ptxas can keep the value in
// one aligned register pair end-to-end (no cross-asm pack/unpack MOVs).
__device__ __forceinline__ ull relu2(ull v) {
    ull r;
    asm("{\n\t"
        ".reg .s32 lo, hi;\n\t"
        "mov.b64 {lo, hi}, %1;\n\t"
        "max.s32 lo, lo, 0;\n\t"
        "max.s32 hi, hi, 0;\n\t"
        "mov.b64 %0, {lo, hi};\n\t"
        "}" : "=l"(r) : "l"(v));
    return r;
}

// duplicate weights into shared as (w, w) pairs -> packed B-operand is one LDS.64
__device__ __forceinline__ void fillw(ull* dst, const float* __restrict__ src,
                                      int n, int tid) {
    for (int i = tid; i < n; i += TPB) {
        float v = src[i];
        dst[i] = pk(v, v);
    }
}

// shared layout offsets (in ull units)
#define O_W11 0
#define O_B11 9
#define O_W12 12
#define O_B12 30
#define O_W13 36
#define O_B13 54
#define O_W21 57
#define O_B21 66
#define O_W22 69
#define O_B22 87
#define O_W23 93
#define O_B23 111
#define O_W31 114
#define O_B31 130
#define O_W32 134
#define O_B32 158
#define O_W33 164
#define O_B33 176
#define SW_TOTAL 178

__global__ __launch_bounds__(TPB, 4)
void cgnn_kernel(const float* __restrict__ u,
                 const float* __restrict__ w11, const float* __restrict__ b11,
                 const float* __restrict__ w12, const float* __restrict__ b12,
                 const float* __restrict__ w13, const float* __restrict__ b13,
                 const float* __restrict__ w21, const float* __restrict__ b21,
                 const float* __restrict__ w22, const float* __restrict__ b22,
                 const float* __restrict__ w23, const float* __restrict__ b23,
                 const float* __restrict__ w31, const float* __restrict__ b31,
                 const float* __restrict__ w32, const float* __restrict__ b32,
                 const float* __restrict__ w33, const float* __restrict__ b33,
                 float* __restrict__ out) {
    __shared__ ull sw[SW_TOTAL];
    const int tid = threadIdx.x;

    fillw(sw + O_W11, w11, 9,  tid);
    fillw(sw + O_B11, b11, 3,  tid);
    fillw(sw + O_W12, w12, 18, tid);
    fillw(sw + O_B12, b12, 6,  tid);
    fillw(sw + O_W13, w13, 18, tid);
    fillw(sw + O_B13, b13, 3,  tid);
    fillw(sw + O_W21, w21, 9,  tid);
    fillw(sw + O_B21, b21, 3,  tid);
    fillw(sw + O_W22, w22, 18, tid);
    fillw(sw + O_B22, b22, 6,  tid);
    fillw(sw + O_W23, w23, 18, tid);
    fillw(sw + O_B23, b23, 3,  tid);
    fillw(sw + O_W31, w31, 16, tid);
    fillw(sw + O_B31, b31, 4,  tid);
    fillw(sw + O_W32, w32, 24, tid);
    fillw(sw + O_B32, b32, 6,  tid);
    fillw(sw + O_W33, w33, 12, tid);
    fillw(sw + O_B33, b33, 2,  tid);
    __syncthreads();

    const int t = blockIdx.x * TPB + tid;
    if (t >= HALF) return;
    const size_t r0 = (size_t)t * 2;  // rows r0 and r0+1

    // load both rows, packed as (row0, row1) pairs
    ull up[24];
    const float4* p = (const float4*)(u + r0 * 24);
#pragma unroll
    for (int q = 0; q < 6; q++) {
        float4 a = p[q];
        float4 b = p[q + 6];
        up[4 * q + 0] = pk(a.x, b.x);
        up[4 * q + 1] = pk(a.y, b.y);
        up[4 * q + 2] = pk(a.z, b.z);
        up[4 * q + 3] = pk(a.w, b.w);
    }

    // ---------------- MLP1: x = u[:, [(2i-1)%24, 2i, 2i+1]], 3->3->6->3 ------
    {
        float4* q0 = (float4*)(out + r0 * 36);
        float4* q1 = (float4*)(out + r0 * 36 + 36);
#pragma unroll
        for (int c = 0; c < 3; c++) {      // 4 windows per chunk -> 12 outputs
            ull o[12];
#pragma unroll
            for (int w = 0; w < 4; w++) {
                const int i = c * 4 + w;
                const ull x0 = up[(2 * i + 23) % 24];
                const ull x1 = up[2 * i];
                const ull x2 = up[2 * i + 1];
                ull h[3];
#pragma unroll
                for (int k = 0; k < 3; k++) {
                    ull a = sw[O_B11 + k];
                    a = ffma2(x0, sw[O_W11 + 0 * 3 + k], a);
                    a = ffma2(x1, sw[O_W11 + 1 * 3 + k], a);
                    a = ffma2(x2, sw[O_W11 + 2 * 3 + k], a);
                    h[k] = relu2(a);
                }
                ull g[6];
#pragma unroll
                for (int k = 0; k < 6; k++) {
                    ull a = sw[O_B12 + k];
#pragma unroll
                    for (int j = 0; j < 3; j++) a = ffma2(h[j], sw[O_W12 + j * 6 + k], a);
                    g[k] = relu2(a);
                }
#pragma unroll
                for (int k = 0; k < 3; k++) {
                    ull a = sw[O_B13 + k];
#pragma unroll
                    for (int j = 0; j < 6; j++) a = ffma2(g[j], sw[O_W13 + j * 3 + k], a);
                    o[w * 3 + k] = a;
                }
            }
            float2 f[12];
#pragma unroll
            for (int k = 0; k < 12; k++) f[k] = unpk(o[k]);
#pragma unroll
            for (int q = 0; q < 3; q++) {
                q0[c * 3 + q] = make_float4(f[4 * q].x, f[4 * q + 1].x, f[4 * q + 2].x, f[4 * q + 3].x);
                q1[c * 3 + q] = make_float4(f[4 * q].y, f[4 * q + 1].y, f[4 * q + 2].y, f[4 * q + 3].y);
            }
        }
    }

    // ---------------- MLP2: x = u[:, [2i, 2i+1, (2i+2)%24]], 3->3->6->3 ------
    {
        float* base = out + (size_t)36 * NROWS;
        float4* q0 = (float4*)(base + r0 * 36);
        float4* q1 = (float4*)(base + r0 * 36 + 36);
#pragma unroll
        for (int c = 0; c < 3; c++) {
            ull o[12];
#pragma unroll
            for (int w = 0; w < 4; w++) {
                const int i = c * 4 + w;
                const ull x0 = up[2 * i];
                const ull x1 = up[2 * i + 1];
                const ull x2 = up[(2 * i + 2) % 24];
                ull h[3];
#pragma unroll
                for (int k = 0; k < 3; k++) {
                    ull a = sw[O_B21 + k];
                    a = ffma2(x0, sw[O_W21 + 0 * 3 + k], a);
                    a = ffma2(x1, sw[O_W21 + 1 * 3 + k], a);
                    a = ffma2(x2, sw[O_W21 + 2 * 3 + k], a);
                    h[k] = relu2(a);
                }
                ull g[6];
#pragma unroll
                for (int k = 0; k < 6; k++) {
                    ull a = sw[O_B22 + k];
#pragma unroll
                    for (int j = 0; j < 3; j++) a = ffma2(h[j], sw[O_W22 + j * 6 + k], a);
                    g[k] = relu2(a);
                }
#pragma unroll
                for (int k = 0; k < 3; k++) {
                    ull a = sw[O_B23 + k];
#pragma unroll
                    for (int j = 0; j < 6; j++) a = ffma2(g[j], sw[O_W23 + j * 3 + k], a);
                    o[w * 3 + k] = a;
                }
            }
            float2 f[12];
#pragma unroll
            for (int k = 0; k < 12; k++) f[k] = unpk(o[k]);
#pragma unroll
            for (int q = 0; q < 3; q++) {
                q0[c * 3 + q] = make_float4(f[4 * q].x, f[4 * q + 1].x, f[4 * q + 2].x, f[4 * q + 3].x);
                q1[c * 3 + q] = make_float4(f[4 * q].y, f[4 * q + 1].y, f[4 * q + 2].y, f[4 * q + 3].y);
            }
        }
    }

    // ---- MLP3: x = u[:, [2i, 2i+1, (2i+2)%24, (2i+3)%24]], 4->4->6->2 -------
    {
        float* base = out + (size_t)72 * NROWS;
        float4* q0 = (float4*)(base + r0 * 24);
        float4* q1 = (float4*)(base + r0 * 24 + 24);
#pragma unroll
        for (int c = 0; c < 3; c++) {      // 4 windows per chunk -> 8 outputs
            ull o[8];
#pragma unroll
            for (int w = 0; w < 4; w++) {
                const int i = c * 4 + w;
                const ull x0 = up[2 * i];
                const ull x1 = up[2 * i + 1];
                const ull x2 = up[(2 * i + 2) % 24];
                const ull x3 = up[(2 * i + 3) % 24];
                ull h[4];
#pragma unroll
                for (int k = 0; k < 4; k++) {
                    ull a = sw[O_B31 + k];
                    a = ffma2(x0, sw[O_W31 + 0 * 4 + k], a);
                    a = ffma2(x1, sw[O_W31 + 1 * 4 + k], a);
                    a = ffma2(x2, sw[O_W31 + 2 * 4 + k], a);
                    a = ffma2(x3, sw[O_W31 + 3 * 4 + k], a);
                    h[k] = relu2(a);
                }
                ull g[6];
#pragma unroll
                for (int k = 0; k < 6; k++) {
                    ull a = sw[O_B32 + k];
#pragma unroll
                    for (int j = 0; j < 4; j++) a = ffma2(h[j], sw[O_W32 + j * 6 + k], a);
                    g[k] = relu2(a);
                }
#pragma unroll
                for (int k = 0; k < 2; k++) {
                    ull a = sw[O_B33 + k];
#pragma unroll
                    for (int j = 0; j < 6; j++) a = ffma2(g[j], sw[O_W33 + j * 2 + k], a);
                    o[w * 2 + k] = a;
                }
            }
            float2 f[8];
#pragma unroll
            for (int k = 0; k < 8; k++) f[k] = unpk(o[k]);
#pragma unroll
            for (int q = 0; q < 2; q++) {
                q0[c * 2 + q] = make_float4(f[4 * q].x, f[4 * q + 1].x, f[4 * q + 2].x, f[4 * q + 3].x);
                q1[c * 2 + q] = make_float4(f[4 * q].y, f[4 * q + 1].y, f[4 * q + 2].y, f[4 * q + 3].y);
            }
        }
    }
}

extern "C" void kernel_launch(void* const* d_in, const int* in_sizes, int n_in,
                              void* d_out, int out_size) {
    const float* u   = (const float*)d_in[0];
    const float* w11 = (const float*)d_in[1];
    const float* b11 = (const float*)d_in[2];
    const float* w12 = (const float*)d_in[3];
    const float* b12 = (const float*)d_in[4];
    const float* w13 = (const float*)d_in[5];
    const float* b13 = (const float*)d_in[6];
    const float* w21 = (const float*)d_in[7];
    const float* b21 = (const float*)d_in[8];
    const float* w22 = (const float*)d_in[9];
    const float* b22 = (const float*)d_in[10];
    const float* w23 = (const float*)d_in[11];
    const float* b23 = (const float*)d_in[12];
    const float* w31 = (const float*)d_in[13];
    const float* b31 = (const float*)d_in[14];
    const float* w32 = (const float*)d_in[15];
    const float* b32 = (const float*)d_in[16];
    const float* w33 = (const float*)d_in[17];
    const float* b33 = (const float*)d_in[18];

    const int blocks = (HALF + TPB - 1) / TPB;
    cgnn_kernel<<<blocks, TPB>>>(u, w11, b11, w12, b12, w13, b13,
                                 w21, b21, w22, b22, w23, b23,
                                 w31, b31, w32, b32, w33, b33,
                                 (float*)d_out);
}

// round 7
// speedup vs baseline: 1.9061x; 1.9061x over previous
#include <cuda_runtime.h>

#define NROWS 1000000
#define NPAIRS (NROWS / 2)          // 500000
#define TPB   128
#define PAIRS_PER_BLOCK TPB         // 128 pairs = 256 rows per block
#define GRID ((NPAIRS + PAIRS_PER_BLOCK - 1) / PAIRS_PER_BLOCK)  // 3907

// padded smem strides (in 32-bit words) -> conflict-free pair access
#define IN_STRIDE  50   // 24 cols * 2 + 2 pad
#define O12_STRIDE 74   // 36 cols * 2 + 2 pad
#define O3_STRIDE  50   // 24 cols * 2 + 2 pad
#define BUF_WORDS (PAIRS_PER_BLOCK * O12_STRIDE)   // 9472 words = 37888 B (max phase)

typedef unsigned long long ull;

__device__ __forceinline__ ull ffma2(ull a, ull b, ull c) {
    ull d;
    asm("fma.rn.f32x2 %0, %1, %2, %3;" : "=l"(d) : "l"(a), "l"(b), "l"(c));
    return d;
}
__device__ __forceinline__ ull pk(float x, float y) {
    ull r;
    asm("mov.b64 %0, {%1, %2};" : "=l"(r) : "f"(x), "f"(y));
    return r;
}
// relu both packed lanes via signed-int max(x,0) (valid for IEEE-754 bits)
__device__ __forceinline__ ull relu2(ull v) {
    ull r;
    asm("{\n\t"
        ".reg .s32 lo, hi;\n\t"
        "mov.b64 {lo, hi}, %1;\n\t"
        "max.s32 lo, lo, 0;\n\t"
        "max.s32 hi, hi, 0;\n\t"
        "mov.b64 %0, {lo, hi};\n\t"
        "}" : "=l"(r) : "l"(v));
    return r;
}

__device__ __forceinline__ void fillw(ull* dst, const float* __restrict__ src,
                                      int n, int tid) {
    for (int i = tid; i < n; i += TPB) {
        float v = src[i];
        dst[i] = pk(v, v);
    }
}

// weight offsets in ull units
#define O_W11 0
#define O_B11 9
#define O_W12 12
#define O_B12 30
#define O_W13 36
#define O_B13 54
#define O_W21 57
#define O_B21 66
#define O_W22 69
#define O_B22 87
#define O_W23 93
#define O_B23 111
#define O_W31 114
#define O_B31 130
#define O_W32 134
#define O_B32 158
#define O_W33 164
#define O_B33 176
#define SW_TOTAL 178

__global__ __launch_bounds__(TPB, 3)
void cgnn_kernel(const float* __restrict__ u,
                 const float* __restrict__ w11, const float* __restrict__ b11,
                 const float* __restrict__ w12, const float* __restrict__ b12,
                 const float* __restrict__ w13, const float* __restrict__ b13,
                 const float* __restrict__ w21, const float* __restrict__ b21,
                 const float* __restrict__ w22, const float* __restrict__ b22,
                 const float* __restrict__ w23, const float* __restrict__ b23,
                 const float* __restrict__ w31, const float* __restrict__ b31,
                 const float* __restrict__ w32, const float* __restrict__ b32,
                 const float* __restrict__ w33, const float* __restrict__ b33,
                 float* __restrict__ out) {
    __shared__ ull   sw[SW_TOTAL];
    __shared__ float buf[BUF_WORDS];        // single staging buffer, reused

    const int tid = threadIdx.x;

    fillw(sw + O_W11, w11, 9,  tid);
    fillw(sw + O_B11, b11, 3,  tid);
    fillw(sw + O_W12, w12, 18, tid);
    fillw(sw + O_B12, b12, 6,  tid);
    fillw(sw + O_W13, w13, 18, tid);
    fillw(sw + O_B13, b13, 3,  tid);
    fillw(sw + O_W21, w21, 9,  tid);
    fillw(sw + O_B21, b21, 3,  tid);
    fillw(sw + O_W22, w22, 18, tid);
    fillw(sw + O_B22, b22, 6,  tid);
    fillw(sw + O_W23, w23, 18, tid);
    fillw(sw + O_B23, b23, 3,  tid);
    fillw(sw + O_W31, w31, 16, tid);
    fillw(sw + O_B31, b31, 4,  tid);
    fillw(sw + O_W32, w32, 24, tid);
    fillw(sw + O_B32, b32, 6,  tid);
    fillw(sw + O_W33, w33, 12, tid);
    fillw(sw + O_B33, b33, 2,  tid);

    const long long R0 = (long long)blockIdx.x * (2 * PAIRS_PER_BLOCK);
    const int npairs = min(PAIRS_PER_BLOCK, NPAIRS - blockIdx.x * PAIRS_PER_BLOCK);
    const int nrows  = npairs * 2;

    // ---- phase 0: coalesced input load -> pair-interleaved smem -------------
    {
        const float4* gin = (const float4*)(u + R0 * 24);
        const int n4 = nrows * 6;  // float4s in this block's input slab
#pragma unroll
        for (int s = 0; s < 12; s++) {
            const int g4 = s * TPB + tid;
            if (g4 < n4) {
                float4 v = gin[g4];
                const int row  = g4 / 6;           // 24 floats = 6 float4 per row
                const int colb = (g4 % 6) * 4;
                float* d = buf + (row >> 1) * IN_STRIDE + (row & 1);
                d[(colb + 0) * 2] = v.x;
                d[(colb + 1) * 2] = v.y;
                d[(colb + 2) * 2] = v.z;
                d[(colb + 3) * 2] = v.w;
            }
        }
    }
    __syncthreads();

    // ---- read this thread's packed row pair into registers ------------------
    ull up[24];
    const bool active = (tid < npairs);
    if (active) {
        const float* src = buf + tid * IN_STRIDE;
#pragma unroll
        for (int j = 0; j < 24; j++)
            up[j] = *(const ull*)(src + 2 * j);
    }
    __syncthreads();   // input fully consumed -> buffer reusable

    // ---------------- MLP1: x = [(2i-1)%24, 2i, 2i+1], 3->3->6->3 ------------
    if (active) {
        float* ob = buf + tid * O12_STRIDE;
#pragma unroll
        for (int i = 0; i < 12; i++) {
            const ull x0 = up[(2 * i + 23) % 24];
            const ull x1 = up[2 * i];
            const ull x2 = up[2 * i + 1];
            ull h[3];
#pragma unroll
            for (int k = 0; k < 3; k++) {
                ull a = sw[O_B11 + k];
                a = ffma2(x0, sw[O_W11 + 0 * 3 + k], a);
                a = ffma2(x1, sw[O_W11 + 1 * 3 + k], a);
                a = ffma2(x2, sw[O_W11 + 2 * 3 + k], a);
                h[k] = relu2(a);
            }
            ull g[6];
#pragma unroll
            for (int k = 0; k < 6; k++) {
                ull a = sw[O_B12 + k];
#pragma unroll
                for (int j = 0; j < 3; j++) a = ffma2(h[j], sw[O_W12 + j * 6 + k], a);
                g[k] = relu2(a);
            }
#pragma unroll
            for (int k = 0; k < 3; k++) {
                ull a = sw[O_B13 + k];
#pragma unroll
                for (int j = 0; j < 6; j++) a = ffma2(g[j], sw[O_W13 + j * 3 + k], a);
                *(ull*)(ob + 2 * (i * 3 + k)) = a;
            }
        }
    }
    __syncthreads();

    // ---- flush out1 (coalesced) ---------------------------------------------
    {
        float4* g1 = (float4*)(out + R0 * 36);
        const int n4 = nrows * 9;
#pragma unroll
        for (int s = 0; s < 18; s++) {
            const int g4 = s * TPB + tid;
            if (g4 < n4) {
                const int row  = g4 / 9;
                const int colb = (g4 % 9) * 4;
                const float* sp = buf + (row >> 1) * O12_STRIDE + (row & 1);
                g1[g4] = make_float4(sp[(colb + 0) * 2], sp[(colb + 1) * 2],
                                     sp[(colb + 2) * 2], sp[(colb + 3) * 2]);
            }
        }
    }
    __syncthreads();

    // ---------------- MLP2: x = [2i, 2i+1, (2i+2)%24], 3->3->6->3 ------------
    if (active) {
        float* ob = buf + tid * O12_STRIDE;
#pragma unroll
        for (int i = 0; i < 12; i++) {
            const ull x0 = up[2 * i];
            const ull x1 = up[2 * i + 1];
            const ull x2 = up[(2 * i + 2) % 24];
            ull h[3];
#pragma unroll
            for (int k = 0; k < 3; k++) {
                ull a = sw[O_B21 + k];
                a = ffma2(x0, sw[O_W21 + 0 * 3 + k], a);
                a = ffma2(x1, sw[O_W21 + 1 * 3 + k], a);
                a = ffma2(x2, sw[O_W21 + 2 * 3 + k], a);
                h[k] = relu2(a);
            }
            ull g[6];
#pragma unroll
            for (int k = 0; k < 6; k++) {
                ull a = sw[O_B22 + k];
#pragma unroll
                for (int j = 0; j < 3; j++) a = ffma2(h[j], sw[O_W22 + j * 6 + k], a);
                g[k] = relu2(a);
            }
#pragma unroll
            for (int k = 0; k < 3; k++) {
                ull a = sw[O_B23 + k];
#pragma unroll
                for (int j = 0; j < 6; j++) a = ffma2(g[j], sw[O_W23 + j * 3 + k], a);
                *(ull*)(ob + 2 * (i * 3 + k)) = a;
            }
        }
    }
    __syncthreads();

    // ---- flush out2 (coalesced) ---------------------------------------------
    {
        float4* g2 = (float4*)(out + (size_t)36 * NROWS + R0 * 36);
        const int n4 = nrows * 9;
#pragma unroll
        for (int s = 0; s < 18; s++) {
            const int g4 = s * TPB + tid;
            if (g4 < n4) {
                const int row  = g4 / 9;
                const int colb = (g4 % 9) * 4;
                const float* sp = buf + (row >> 1) * O12_STRIDE + (row & 1);
                g2[g4] = make_float4(sp[(colb + 0) * 2], sp[(colb + 1) * 2],
                                     sp[(colb + 2) * 2], sp[(colb + 3) * 2]);
            }
        }
    }
    __syncthreads();

    // ---- MLP3: x = [2i, 2i+1, (2i+2)%24, (2i+3)%24], 4->4->6->2 -------------
    if (active) {
        float* ob = buf + tid * O3_STRIDE;
#pragma unroll
        for (int i = 0; i < 12; i++) {
            const ull x0 = up[2 * i];
            const ull x1 = up[2 * i + 1];
            const ull x2 = up[(2 * i + 2) % 24];
            const ull x3 = up[(2 * i + 3) % 24];
            ull h[4];
#pragma unroll
            for (int k = 0; k < 4; k++) {
                ull a = sw[O_B31 + k];
                a = ffma2(x0, sw[O_W31 + 0 * 4 + k], a);
                a = ffma2(x1, sw[O_W31 + 1 * 4 + k], a);
                a = ffma2(x2, sw[O_W31 + 2 * 4 + k], a);
                a = ffma2(x3, sw[O_W31 + 3 * 4 + k], a);
                h[k] = relu2(a);
            }
            ull g[6];
#pragma unroll
            for (int k = 0; k < 6; k++) {
                ull a = sw[O_B32 + k];
#pragma unroll
                for (int j = 0; j < 4; j++) a = ffma2(h[j], sw[O_W32 + j * 6 + k], a);
                g[k] = relu2(a);
            }
#pragma unroll
            for (int k = 0; k < 2; k++) {
                ull a = sw[O_B33 + k];
#pragma unroll
                for (int j = 0; j < 6; j++) a = ffma2(g[j], sw[O_W33 + j * 2 + k], a);
                *(ull*)(ob + 2 * (i * 2 + k)) = a;
            }
        }
    }
    __syncthreads();

    // ---- flush out3 (coalesced) ---------------------------------------------
    {
        float4* g3 = (float4*)(out + (size_t)72 * NROWS + R0 * 24);
        const int n4 = nrows * 6;
#pragma unroll
        for (int s = 0; s < 12; s++) {
            const int g4 = s * TPB + tid;
            if (g4 < n4) {
                const int row  = g4 / 6;
                const int colb = (g4 % 6) * 4;
                const float* sp = buf + (row >> 1) * O3_STRIDE + (row & 1);
                g3[g4] = make_float4(sp[(colb + 0) * 2], sp[(colb + 1) * 2],
                                     sp[(colb + 2) * 2], sp[(colb + 3) * 2]);
            }
        }
    }
}

extern "C" void kernel_launch(void* const* d_in, const int* in_sizes, int n_in,
                              void* d_out, int out_size) {
    const float* u   = (const float*)d_in[0];
    const float* w11 = (const float*)d_in[1];
    const float* b11 = (const float*)d_in[2];
    const float* w12 = (const float*)d_in[3];
    const float* b12 = (const float*)d_in[4];
    const float* w13 = (const float*)d_in[5];
    const float* b13 = (const float*)d_in[6];
    const float* w21 = (const float*)d_in[7];
    const float* b21 = (const float*)d_in[8];
    const float* w22 = (const float*)d_in[9];
    const float* b22 = (const float*)d_in[10];
    const float* w23 = (const float*)d_in[11];
    const float* b23 = (const float*)d_in[12];
    const float* w31 = (const float*)d_in[13];
    const float* b31 = (const float*)d_in[14];
    const float* w32 = (const float*)d_in[15];
    const float* b32 = (const float*)d_in[16];
    const float* w33 = (const float*)d_in[17];
    const float* b33 = (const float*)d_in[18];

    cgnn_kernel<<<GRID, TPB>>>(u, w11, b11, w12, b12, w13, b13,
                               w21, b21, w22, b22, w23, b23,
                               w31, b31, w32, b32, w33, b33,
                               (float*)d_out);
}